// round 6
// baseline (speedup 1.0000x reference)
#include <cuda_runtime.h>
#include <cstdint>

#define NPTS 8192
#define FDIM 512
#define SEGS 32
#define SEGREFS 256

typedef unsigned long long ull;

// ---- device scratch (no allocations allowed) ----
__device__ float g_emb[1024 * NPTS];
__device__ float g_h1[2][640 * NPTS];
__device__ float g_h2[2][256 * NPTS];
__device__ float g_h3[2][128 * NPTS];
__device__ int   g_idx[NPTS];
__device__ ulonglong2 g_refp[NPTS / 2][2];   // {x01,y01},{z01,r2_01}
__device__ ull   g_part[SEGS * NPTS];

// ---- f32x2 helpers ----
__device__ __forceinline__ ull pack2(float lo, float hi) {
    ull r; asm("mov.b64 %0, {%1, %2};" : "=l"(r) : "f"(lo), "f"(hi)); return r;
}
__device__ __forceinline__ void unpack2(ull v, float& lo, float& hi) {
    asm("mov.b64 {%0, %1}, %2;" : "=f"(lo), "=f"(hi) : "l"(v));
}
__device__ __forceinline__ ull fma2(ull a, ull b, ull c) {
    ull d; asm("fma.rn.f32x2 %0, %1, %2, %3;" : "=l"(d) : "l"(a), "l"(b), "l"(c)); return d;
}
__device__ __forceinline__ ull mul2(ull a, ull b) {
    ull d; asm("mul.rn.f32x2 %0, %1, %2;" : "=l"(d) : "l"(a), "l"(b)); return d;
}
__device__ __forceinline__ ull add2(ull a, ull b) {
    ull d; asm("add.rn.f32x2 %0, %1, %2;" : "=l"(d) : "l"(a), "l"(b)); return d;
}
// monotone float->uint map (handles negatives from cancellation)
__device__ __forceinline__ unsigned mono(float f) {
    unsigned b = __float_as_uint(f);
    return (b & 0x80000000u) ? ~b : (b | 0x80000000u);
}

// ---- KNN prep: pack refs + |r|^2, reference rounding: fl(fl(x2+y2)+z2) ----
__global__ void prep_kernel(const float* __restrict__ t1) {
    int p = blockIdx.x * 256 + threadIdx.x;
    if (p >= NPTS / 2) return;
    int i0 = 2 * p, i1 = i0 + 1;
    float x0 = t1[i0], y0 = t1[NPTS + i0], z0 = t1[2 * NPTS + i0];
    float x1 = t1[i1], y1 = t1[NPTS + i1], z1 = t1[2 * NPTS + i1];
    float r20 = __fadd_rn(__fadd_rn(__fmul_rn(x0, x0), __fmul_rn(y0, y0)), __fmul_rn(z0, z0));
    float r21 = __fadd_rn(__fadd_rn(__fmul_rn(x1, x1), __fmul_rn(y1, y1)), __fmul_rn(z1, z1));
    ulonglong2 e0, e1;
    e0.x = pack2(x0, x1); e0.y = pack2(y0, y1);
    e1.x = pack2(z0, z1); e1.y = pack2(r20, r21);
    g_refp[p][0] = e0;
    g_refp[p][1] = e1;
}

// ---- KNN partial argmin over one 256-ref segment for 512 queries ----
__global__ void __launch_bounds__(256)
knn_partial_kernel(const float* __restrict__ t2) {
    __shared__ ulonglong2 s_ref[SEGREFS / 2][2];
    const int tid = threadIdx.x;
    const int seg = blockIdx.y;
    s_ref[tid >> 1][tid & 1] = g_refp[seg * (SEGREFS / 2) + (tid >> 1)][tid & 1];

    const int q0 = blockIdx.x * 512 + tid;
    ull axn[2], ayn[2], azn[2], q2p[2];
#pragma unroll
    for (int s = 0; s < 2; ++s) {
        int q = q0 + s * 256;
        float qx = t2[q], qy = t2[NPTS + q], qz = t2[2 * NPTS + q];
        float q2 = __fadd_rn(__fadd_rn(__fmul_rn(qx, qx), __fmul_rn(qy, qy)), __fmul_rn(qz, qz));
        float ax = __fmul_rn(qx, -2.0f), ay = __fmul_rn(qy, -2.0f), az = __fmul_rn(qz, -2.0f);
        axn[s] = pack2(ax, ax); ayn[s] = pack2(ay, ay); azn[s] = pack2(az, az);
        q2p[s] = pack2(q2, q2);
    }
    float best[2][8]; int bi[2][8];
#pragma unroll
    for (int s = 0; s < 2; ++s)
#pragma unroll
        for (int c = 0; c < 8; ++c) { best[s][c] = __int_as_float(0x7f800000); bi[s][c] = 0x7fffffff; }
    __syncthreads();

    const int gbase = seg * SEGREFS;
    for (int pg = 0; pg < SEGREFS / 2; pg += 4) {
#pragma unroll
        for (int u = 0; u < 4; ++u) {
            const int p = pg + u;
            const ulonglong2 e0 = s_ref[p][0];
            const ulonglong2 e1 = s_ref[p][1];
            const int ib = gbase + p * 2;
#pragma unroll
            for (int s = 0; s < 2; ++s) {
                // -2g = fma(z,-2Z, fma(y,-2Y, x*(-2X))): exact -2 scaling of ref chain
                ull g2 = fma2(e1.x, azn[s], fma2(e0.y, ayn[s], mul2(e0.x, axn[s])));
                ull sv = add2(e1.y, q2p[s]);   // fl(r2+q2)
                ull d  = add2(sv, g2);         // fl((r2+q2)-2g)
                float dlo, dhi; unpack2(d, dlo, dhi);
                if (dlo < best[s][2 * u])     { best[s][2 * u] = dlo;     bi[s][2 * u] = ib; }
                if (dhi < best[s][2 * u + 1]) { best[s][2 * u + 1] = dhi; bi[s][2 * u + 1] = ib + 1; }
            }
        }
    }
#pragma unroll
    for (int s = 0; s < 2; ++s) {
        ull m = ~0ull;
#pragma unroll
        for (int c = 0; c < 8; ++c) {
            ull key = ((ull)mono(best[s][c]) << 32) | (unsigned)bi[s][c];
            if (key < m) m = key;   // lexicographic (d, idx): first-min semantics
        }
        g_part[(size_t)seg * NPTS + q0 + s * 256] = m;
    }
}

__global__ void knn_reduce_kernel() {
    int q = blockIdx.x * 256 + threadIdx.x;
    ull m = ~0ull;
#pragma unroll
    for (int s = 0; s < SEGS; ++s) {
        ull v = g_part[(size_t)s * NPTS + q];
        if (v < m) m = v;
    }
    g_idx[q] = (int)(unsigned)(m & 0xffffffffu);
}

// ---- gather + concat: g_emb = [emb1[:, idx] ; emb2] ----
__global__ void gather_kernel(const float* __restrict__ emb1, const float* __restrict__ emb2) {
    int n = blockIdx.x * 256 + threadIdx.x;
    int k = blockIdx.y;
    float v = (k < FDIM) ? emb1[k * NPTS + g_idx[n]] : emb2[(k - FDIM) * NPTS + n];
    g_emb[k * NPTS + n] = v;
}

// ---- GEMM + bias + relu: Y = relu(W @ X + b), W:(M,K) rm, X:(K,8192) rm ----
// 128x128 tile, BK=16, 256 thr, 8x8 microtile as 8x4 f32x2 accumulators.
__global__ void __launch_bounds__(256)
gemm_relu_kernel(const float* __restrict__ W, const float* __restrict__ Bi,
                 const float* __restrict__ X, float* __restrict__ Y, int K) {
    __shared__ float Ws[16][133];     // Ws[k][m]
    __shared__ ull   Xs[16][64];      // packed n-pairs
    const int tid = threadIdx.x;
    const int m0 = blockIdx.y * 128;
    const int n0 = blockIdx.x * 128;
    const int tm = (tid >> 4) * 8;
    const int tn2 = (tid & 15) * 4;   // 4 packed pairs = 8 n's

    ull acc[8][4];
#pragma unroll
    for (int i = 0; i < 8; ++i)
#pragma unroll
        for (int j = 0; j < 4; ++j) acc[i][j] = 0ull;

    for (int k0 = 0; k0 < K; k0 += 16) {
#pragma unroll
        for (int j = 0; j < 2; ++j) {
            int id = j * 256 + tid;                 // 512 float4 chunks of W tile
            int m = id >> 2, kq = id & 3;
            float4 w = *(const float4*)&W[(size_t)(m0 + m) * K + k0 + kq * 4];
            Ws[kq * 4 + 0][m] = w.x; Ws[kq * 4 + 1][m] = w.y;
            Ws[kq * 4 + 2][m] = w.z; Ws[kq * 4 + 3][m] = w.w;
            int row = id >> 5, c2 = id & 31;        // 512 16B chunks of X tile
            const ulonglong2* src = (const ulonglong2*)&X[(size_t)(k0 + row) * NPTS + n0];
            ((ulonglong2*)&Xs[row][0])[c2] = src[c2];
        }
        __syncthreads();
#pragma unroll
        for (int kk = 0; kk < 16; ++kk) {
            ull x[4];
            ulonglong2 xa = *(const ulonglong2*)&Xs[kk][tn2];
            ulonglong2 xb = *(const ulonglong2*)&Xs[kk][tn2 + 2];
            x[0] = xa.x; x[1] = xa.y; x[2] = xb.x; x[3] = xb.y;
#pragma unroll
            for (int i = 0; i < 8; ++i) {
                float a = Ws[kk][tm + i];
                ull ap = pack2(a, a);
#pragma unroll
                for (int j = 0; j < 4; ++j) acc[i][j] = fma2(ap, x[j], acc[i][j]);
            }
        }
        __syncthreads();
    }
#pragma unroll
    for (int i = 0; i < 8; ++i) {
        float b = Bi[m0 + tm + i];
        float* yr = &Y[(size_t)(m0 + tm + i) * NPTS + n0 + tn2 * 2];
        float v[8];
#pragma unroll
        for (int j = 0; j < 4; ++j) {
            float lo, hi; unpack2(acc[i][j], lo, hi);
            v[2 * j] = fmaxf(lo + b, 0.0f);
            v[2 * j + 1] = fmaxf(hi + b, 0.0f);
        }
        *(float4*)&yr[0] = make_float4(v[0], v[1], v[2], v[3]);
        *(float4*)&yr[4] = make_float4(v[4], v[5], v[6], v[7]);
    }
}

// ---- layer 4: only obj-selected rows, no relu ----
__global__ void __launch_bounds__(256)
final_kernel(const float* __restrict__ w4r, const float* __restrict__ b4r,
             const float* __restrict__ w4t, const float* __restrict__ b4t,
             const int* __restrict__ obj, float* __restrict__ out) {
    __shared__ float wr[4][128], wt[3][128];
    const int tid = threadIdx.x;
    const int o = obj[0];
    if (tid < 128) {
#pragma unroll
        for (int q = 0; q < 4; ++q) wr[q][tid] = w4r[(size_t)(o * 4 + q) * 128 + tid];
#pragma unroll
        for (int q = 0; q < 3; ++q) wt[q][tid] = w4t[(size_t)(o * 3 + q) * 128 + tid];
    }
    __syncthreads();
    const int n = blockIdx.x * 256 + tid;
    float ar[4], at[3];
#pragma unroll
    for (int q = 0; q < 4; ++q) ar[q] = b4r[o * 4 + q];
#pragma unroll
    for (int q = 0; q < 3; ++q) at[q] = b4t[o * 3 + q];
    for (int k = 0; k < 128; ++k) {
        float xr = g_h3[0][(size_t)k * NPTS + n];
        float xt = g_h3[1][(size_t)k * NPTS + n];
#pragma unroll
        for (int q = 0; q < 4; ++q) ar[q] = fmaf(wr[q][k], xr, ar[q]);
#pragma unroll
        for (int q = 0; q < 3; ++q) at[q] = fmaf(wt[q][k], xt, at[q]);
    }
#pragma unroll
    for (int q = 0; q < 4; ++q) out[(size_t)n * 4 + q] = ar[q];
    float* ot = out + 4 * NPTS;
#pragma unroll
    for (int q = 0; q < 3; ++q) ot[(size_t)n * 3 + q] = at[q];
}

extern "C" void kernel_launch(void* const* d_in, const int* in_sizes, int n_in,
                              void* d_out, int out_size) {
    const float* emb1 = (const float*)d_in[0];
    const float* emb2 = (const float*)d_in[1];
    const float* t1   = (const float*)d_in[2];
    const float* t2   = (const float*)d_in[3];
    const int*   obj  = (const int*)d_in[4];
    const float* w1r = (const float*)d_in[5],  *b1r = (const float*)d_in[6];
    const float* w2r = (const float*)d_in[7],  *b2r = (const float*)d_in[8];
    const float* w3r = (const float*)d_in[9],  *b3r = (const float*)d_in[10];
    const float* w4r = (const float*)d_in[11], *b4r = (const float*)d_in[12];
    const float* w1t = (const float*)d_in[13], *b1t = (const float*)d_in[14];
    const float* w2t = (const float*)d_in[15], *b2t = (const float*)d_in[16];
    const float* w3t = (const float*)d_in[17], *b3t = (const float*)d_in[18];
    const float* w4t = (const float*)d_in[19], *b4t = (const float*)d_in[20];
    float* out = (float*)d_out;

    float *p_emb, *p_h1, *p_h2, *p_h3;
    cudaGetSymbolAddress((void**)&p_emb, g_emb);
    cudaGetSymbolAddress((void**)&p_h1, g_h1);
    cudaGetSymbolAddress((void**)&p_h2, g_h2);
    cudaGetSymbolAddress((void**)&p_h3, g_h3);
    float* h1r = p_h1;              float* h1t = p_h1 + 640 * NPTS;
    float* h2r = p_h2;              float* h2t = p_h2 + 256 * NPTS;
    float* h3r = p_h3;              float* h3t = p_h3 + 128 * NPTS;

    prep_kernel<<<(NPTS / 2 + 255) / 256, 256>>>(t1);
    knn_partial_kernel<<<dim3(16, SEGS), 256>>>(t2);
    knn_reduce_kernel<<<NPTS / 256, 256>>>();
    gather_kernel<<<dim3(NPTS / 256, 1024), 256>>>(emb1, emb2);

    gemm_relu_kernel<<<dim3(64, 5), 256>>>(w1r, b1r, p_emb, h1r, 1024);
    gemm_relu_kernel<<<dim3(64, 5), 256>>>(w1t, b1t, p_emb, h1t, 1024);
    gemm_relu_kernel<<<dim3(64, 2), 256>>>(w2r, b2r, h1r, h2r, 640);
    gemm_relu_kernel<<<dim3(64, 2), 256>>>(w2t, b2t, h1t, h2t, 640);
    gemm_relu_kernel<<<dim3(64, 1), 256>>>(w3r, b3r, h2r, h3r, 256);
    gemm_relu_kernel<<<dim3(64, 1), 256>>>(w3t, b3t, h2t, h3t, 256);

    final_kernel<<<NPTS / 256, 256>>>(w4r, b4r, w4t, b4t, obj, out);
}